// round 5
// baseline (speedup 1.0000x reference)
#include <cuda_runtime.h>

// Problem constants
#define BATCH   8
#define T_SEQ   512
#define DMODEL  1024
#define NH      16
#define DK      64
#define S_REL   1023          // 2T-1
#define BT      (BATCH*T_SEQ) // 4096
#define THREE_D (3*DMODEL)    // 3072

typedef unsigned long long u64;

__device__ __forceinline__ void ffma2(u64 &d, u64 a, u64 b) {
    asm("fma.rn.f32x2 %0, %1, %2, %0;" : "+l"(d) : "l"(a), "l"(b));
}
__device__ __forceinline__ float2 unpack2(u64 v) {
    float2 r;
    asm("mov.b64 {%0, %1}, %2;" : "=f"(r.x), "=f"(r.y) : "l"(v));
    return r;
}

// Scratch (device globals; no allocation allowed)
__device__ float g_qkv[BT * THREE_D];   // [B,T, 3D]  (q | k | v per row)
__device__ float g_p[S_REL * DMODEL];   // [S, D] positional projection
__device__ float g_ctx[BT * DMODEL];    // [B,T,D] attention context

// ---------------------------------------------------------------------------
// SGEMM (NT): C[M,N] = A[M,K] @ B[N,K]^T + bias[N]
// 128x128 tile, BK=8, 256 threads, 8x(4x2) per thread via fma.rn.f32x2.
// A is staged duplicated ({v,v} pairs) so the FFMA2 a-operand needs no packs.
// ---------------------------------------------------------------------------
__global__ __launch_bounds__(256, 2)
void sgemm_nt(const float* __restrict__ A, const float* __restrict__ Bm,
              const float* __restrict__ bias, float* __restrict__ C,
              int M, int N, int K)
{
    __shared__ __align__(16) float As2[8][256];  // [k][2*row] duplicated
    __shared__ __align__(16) float Bs[8][128];   // [k][col]

    const int tid  = threadIdx.x;
    const int m0   = blockIdx.y * 128;
    const int n0   = blockIdx.x * 128;
    const int tx   = tid & 15;
    const int ty   = tid >> 4;
    const int lrow = tid >> 1;          // 0..127
    const int lcol = (tid & 1) * 4;     // 0 or 4

    u64 acc2[8][4];                     // [i][j-pair]: lanes = cols 2j, 2j+1
#pragma unroll
    for (int i = 0; i < 8; i++)
#pragma unroll
        for (int j = 0; j < 4; j++) acc2[i][j] = 0ull;

    for (int k0 = 0; k0 < K; k0 += 8) {
        float4 av = make_float4(0.f, 0.f, 0.f, 0.f);
        if (m0 + lrow < M)
            av = *(const float4*)(A + (size_t)(m0 + lrow) * K + k0 + lcol);
        float4 bv = make_float4(0.f, 0.f, 0.f, 0.f);
        if (n0 + lrow < N)
            bv = *(const float4*)(Bm + (size_t)(n0 + lrow) * K + k0 + lcol);
        *(float2*)&As2[lcol + 0][2 * lrow] = make_float2(av.x, av.x);
        *(float2*)&As2[lcol + 1][2 * lrow] = make_float2(av.y, av.y);
        *(float2*)&As2[lcol + 2][2 * lrow] = make_float2(av.z, av.z);
        *(float2*)&As2[lcol + 3][2 * lrow] = make_float2(av.w, av.w);
        Bs[lcol + 0][lrow] = bv.x; Bs[lcol + 1][lrow] = bv.y;
        Bs[lcol + 2][lrow] = bv.z; Bs[lcol + 3][lrow] = bv.w;
        __syncthreads();
#pragma unroll
        for (int k = 0; k < 8; k++) {
            u64 a2[8], b2[4];
            const u64* ap = (const u64*)&As2[k][ty * 16];
            const u64* bp = (const u64*)&Bs[k][tx * 8];
#pragma unroll
            for (int i = 0; i < 8; i++) a2[i] = ap[i];
#pragma unroll
            for (int j = 0; j < 4; j++) b2[j] = bp[j];
#pragma unroll
            for (int i = 0; i < 8; i++)
#pragma unroll
                for (int j = 0; j < 4; j++)
                    ffma2(acc2[i][j], a2[i], b2[j]);
        }
        __syncthreads();
    }

#pragma unroll
    for (int i = 0; i < 8; i++) {
        int row = m0 + ty * 8 + i;
        if (row < M) {
            int col = n0 + tx * 8;
            float2 p0 = unpack2(acc2[i][0]);
            float2 p1 = unpack2(acc2[i][1]);
            float2 p2 = unpack2(acc2[i][2]);
            float2 p3 = unpack2(acc2[i][3]);
            float4 v0, v1;
            v0.x = p0.x; v0.y = p0.y; v0.z = p1.x; v0.w = p1.y;
            v1.x = p2.x; v1.y = p2.y; v1.z = p3.x; v1.w = p3.y;
            if (bias) {
                const float4 bb0 = *(const float4*)(bias + col);
                const float4 bb1 = *(const float4*)(bias + col + 4);
                v0.x += bb0.x; v0.y += bb0.y; v0.z += bb0.z; v0.w += bb0.w;
                v1.x += bb1.x; v1.y += bb1.y; v1.z += bb1.z; v1.w += bb1.w;
            }
            *(float4*)(C + (size_t)row * N + col)     = v0;
            *(float4*)(C + (size_t)row * N + col + 4) = v1;
        }
    }
}

// ---------------------------------------------------------------------------
// Attention: per block = (b, h, 32 query rows).
//   AC[t,s]  = (q[t]+posu) . k[s]        (4 s-tiles of 128)
//   BD via diagonal GEMM: c[t,j] = (q[t]+posv) . p[j+511], scatter to s=t+j
// Dot products use f32x2 paired along d (reduction); final = lo+hi.
// Row pitch 66 (even) so u64 shared loads stay 8B-aligned.
// smem: qu(32x66) + qv(32x66) + buf(128x66) + scores(32x512)
// ---------------------------------------------------------------------------
#define ATTN_SMEM ((32*66*2 + 128*66 + 32*512) * 4)   // 116224 bytes

__global__ __launch_bounds__(256, 1)
void attn_kernel(const float* __restrict__ posu, const float* __restrict__ posv,
                 const int* __restrict__ mask,
                 float* __restrict__ weights)
{
    const int bid   = blockIdx.x;          // 2048 blocks
    const int ttile = bid & 15;
    const int h     = (bid >> 4) & 15;
    const int b     = bid >> 8;
    const int t0    = ttile * 32;

    extern __shared__ __align__(16) float sm[];
    float* qu  = sm;                 // 32 x 66
    float* qv  = qu + 32 * 66;       // 32 x 66
    float* buf = qv + 32 * 66;       // 128 x 66
    float* sc  = buf + 128 * 66;     // 32 x 512

    const int tid = threadIdx.x;
    const int tx  = tid & 31;
    const int ty  = tid >> 5;

    // load q tile, add posu/posv
#pragma unroll
    for (int i = 0; i < 8; i++) {
        int e  = i * 256 + tid;       // 0..2047
        int tt = e >> 6;
        int d  = e & 63;
        float qval = g_qkv[(size_t)(b * T_SEQ + t0 + tt) * THREE_D + h * DK + d];
        qu[tt * 66 + d] = qval + posu[h * DK + d];
        qv[tt * 66 + d] = qval + posv[h * DK + d];
    }
    __syncthreads();

    // ---------------- AC pass: scores[t][s] = qu[t].k[s] ----------------
    for (int st = 0; st < 4; st++) {
        const int s0 = st * 128;
#pragma unroll
        for (int i = 0; i < 32; i++) {
            int e  = i * 256 + tid;
            int ss = e >> 6;
            int d  = e & 63;
            buf[ss * 66 + d] =
                g_qkv[(size_t)(b * T_SEQ + s0 + ss) * THREE_D + DMODEL + h * DK + d];
        }
        __syncthreads();

        u64 acc2[4][4];
#pragma unroll
        for (int i = 0; i < 4; i++)
#pragma unroll
            for (int j = 0; j < 4; j++) acc2[i][j] = 0ull;

#pragma unroll 4
        for (int dp = 0; dp < 32; dp++) {      // d-pair index
            u64 a2[4], b2[4];
#pragma unroll
            for (int i = 0; i < 4; i++)
                a2[i] = *(const u64*)&qu[(ty * 4 + i) * 66 + 2 * dp];
#pragma unroll
            for (int j = 0; j < 4; j++)
                b2[j] = *(const u64*)&buf[(tx + 32 * j) * 66 + 2 * dp];
#pragma unroll
            for (int i = 0; i < 4; i++)
#pragma unroll
                for (int j = 0; j < 4; j++)
                    ffma2(acc2[i][j], a2[i], b2[j]);
        }
#pragma unroll
        for (int i = 0; i < 4; i++)
#pragma unroll
            for (int j = 0; j < 4; j++) {
                float2 p = unpack2(acc2[i][j]);
                sc[(ty * 4 + i) * 512 + s0 + tx + j * 32] = p.x + p.y;
            }
        __syncthreads();
    }

    // ---------------- BD pass (diagonal): c[t,j] = qv[t].p[j+511] --------
    const int jlo = -(t0 + 31);
    for (int jt = 0; jt < 5; jt++) {
        const int j0 = jlo + jt * 128;
#pragma unroll
        for (int i = 0; i < 32; i++) {
            int e = i * 256 + tid;
            int r = e >> 6;
            int d = e & 63;
            int prow = j0 + r + (T_SEQ - 1);
            buf[r * 66 + d] = (prow >= 0 && prow < S_REL)
                ? g_p[(size_t)prow * DMODEL + h * DK + d] : 0.f;
        }
        __syncthreads();

        u64 acc2[4][4];
#pragma unroll
        for (int i = 0; i < 4; i++)
#pragma unroll
            for (int j = 0; j < 4; j++) acc2[i][j] = 0ull;

#pragma unroll 4
        for (int dp = 0; dp < 32; dp++) {
            u64 a2[4], b2[4];
#pragma unroll
            for (int i = 0; i < 4; i++)
                a2[i] = *(const u64*)&qv[(ty * 4 + i) * 66 + 2 * dp];
#pragma unroll
            for (int j = 0; j < 4; j++)
                b2[j] = *(const u64*)&buf[(tx + 32 * j) * 66 + 2 * dp];
#pragma unroll
            for (int i = 0; i < 4; i++)
#pragma unroll
                for (int j = 0; j < 4; j++)
                    ffma2(acc2[i][j], a2[i], b2[j]);
        }
#pragma unroll
        for (int i = 0; i < 4; i++) {
            int tt = ty * 4 + i;
#pragma unroll
            for (int j = 0; j < 4; j++) {
                int jglob = j0 + tx + j * 32;
                int s = t0 + tt + jglob;          // global key index
                if (s >= 0 && s < T_SEQ) {
                    float2 p = unpack2(acc2[i][j]);
                    sc[tt * 512 + s] += p.x + p.y;
                }
            }
        }
        __syncthreads();
    }

    // ---------------- scale + mask + softmax + write weights -------------
    const int wid  = tid >> 5;
    const int lane = tid & 31;
#pragma unroll
    for (int rr = 0; rr < 4; rr++) {
        const int tt = wid * 4 + rr;
        const int t  = t0 + tt;
        const int* mrow = mask + ((size_t)b * T_SEQ + t) * T_SEQ;

        float mx = -3.4e38f;
        for (int c = lane; c < T_SEQ; c += 32) {
            float v = sc[tt * 512 + c] * 0.125f;       // 1/sqrt(64)
            v = mrow[c] ? v : -100000.0f;
            sc[tt * 512 + c] = v;
            mx = fmaxf(mx, v);
        }
#pragma unroll
        for (int off = 16; off > 0; off >>= 1)
            mx = fmaxf(mx, __shfl_xor_sync(0xffffffffu, mx, off));

        float sum = 0.f;
        for (int c = lane; c < T_SEQ; c += 32) {
            float e = __expf(sc[tt * 512 + c] - mx);
            sc[tt * 512 + c] = e;
            sum += e;
        }
#pragma unroll
        for (int off = 16; off > 0; off >>= 1)
            sum += __shfl_xor_sync(0xffffffffu, sum, off);
        float inv = 1.f / sum;

        float* wrow = weights + (((size_t)b * NH + h) * T_SEQ + t) * T_SEQ;
        for (int c = lane; c < T_SEQ; c += 32)
            wrow[c] = sc[tt * 512 + c] * inv;
    }
}

// ---------------------------------------------------------------------------
// ctx[b,t,h,:] = sum_s weights[b,h,t,s] * v[b,s,h,:]
// block = (b, h, 64 t-rows); 256 threads; f32x2 paired along s (reduction).
// V tile stored transposed (vsT[d][s]) so both operands are s-contiguous.
// ---------------------------------------------------------------------------
__global__ __launch_bounds__(256, 2)
void ctx_kernel(const float* __restrict__ weights)
{
    const int bid   = blockIdx.x;          // 1024 blocks
    const int ttile = bid & 7;
    const int h     = (bid >> 3) & 15;
    const int b     = bid >> 7;
    const int t0    = ttile * 64;

    __shared__ __align__(16) float ws[64][66];   // [t][s]
    __shared__ __align__(16) float vsT[64][66];  // [d][s]

    const int tid = threadIdx.x;
    const int tx  = tid & 15;
    const int ty  = tid >> 4;

    u64 acc2[4][4];
#pragma unroll
    for (int i = 0; i < 4; i++)
#pragma unroll
        for (int j = 0; j < 4; j++) acc2[i][j] = 0ull;

    const float* wbase = weights + (((size_t)b * NH + h) * T_SEQ + t0) * T_SEQ;

    for (int s0 = 0; s0 < T_SEQ; s0 += 64) {
#pragma unroll
        for (int i = 0; i < 16; i++) {
            int e = i * 256 + tid;
            int r = e >> 6;
            int c = e & 63;
            ws[r][c] = wbase[(size_t)r * T_SEQ + s0 + c];
        }
#pragma unroll
        for (int i = 0; i < 16; i++) {
            int e = i * 256 + tid;
            int r = e >> 6;   // s index
            int c = e & 63;   // d index
            vsT[c][r] = g_qkv[(size_t)(b * T_SEQ + s0 + r) * THREE_D + 2 * DMODEL + h * DK + c];
        }
        __syncthreads();
#pragma unroll 4
        for (int sp = 0; sp < 32; sp++) {      // s-pair index
            u64 a2[4], b2[4];
#pragma unroll
            for (int i = 0; i < 4; i++)
                a2[i] = *(const u64*)&ws[ty * 4 + i][2 * sp];
#pragma unroll
            for (int j = 0; j < 4; j++)
                b2[j] = *(const u64*)&vsT[tx + 16 * j][2 * sp];
#pragma unroll
            for (int i = 0; i < 4; i++)
#pragma unroll
                for (int j = 0; j < 4; j++)
                    ffma2(acc2[i][j], a2[i], b2[j]);
        }
        __syncthreads();
    }
#pragma unroll
    for (int i = 0; i < 4; i++) {
        int t = t0 + ty * 4 + i;
#pragma unroll
        for (int j = 0; j < 4; j++) {
            int d = tx + j * 16;
            float2 p = unpack2(acc2[i][j]);
            g_ctx[(size_t)(b * T_SEQ + t) * DMODEL + h * DK + d] = p.x + p.y;
        }
    }
}

// ---------------------------------------------------------------------------
extern "C" void kernel_launch(void* const* d_in, const int* in_sizes, int n_in,
                              void* d_out, int out_size)
{
    const float* x    = (const float*)d_in[0];
    const int*   mask = (const int*)d_in[1];
    const float* pos  = (const float*)d_in[2];
    const float* Wqkv = (const float*)d_in[3];
    const float* bqkv = (const float*)d_in[4];
    const float* Wpos = (const float*)d_in[5];
    const float* posu = (const float*)d_in[6];
    const float* posv = (const float*)d_in[7];
    const float* Wout = (const float*)d_in[8];
    const float* bout = (const float*)d_in[9];

    float* out     = (float*)d_out;
    float* weights = out + (size_t)BT * DMODEL;   // tuple: (out, weights)

    float* qkv_buf; cudaGetSymbolAddress((void**)&qkv_buf, g_qkv);
    float* p_buf;   cudaGetSymbolAddress((void**)&p_buf,   g_p);
    float* ctx_buf; cudaGetSymbolAddress((void**)&ctx_buf, g_ctx);

    // 1) QKV projection: [4096,3072] = x[4096,1024] @ Wqkv[3072,1024]^T + bqkv
    {
        dim3 grid(THREE_D / 128, BT / 128);
        sgemm_nt<<<grid, 256>>>(x, Wqkv, bqkv, qkv_buf, BT, THREE_D, DMODEL);
    }
    // 2) positional projection: [1023,1024] = pos @ Wpos^T (no bias)
    {
        dim3 grid(DMODEL / 128, (S_REL + 127) / 128);
        sgemm_nt<<<grid, 256>>>(pos, Wpos, nullptr, p_buf, S_REL, DMODEL, DMODEL);
    }
    // 3) attention scores + softmax -> weights
    {
        cudaFuncSetAttribute(attn_kernel,
                             cudaFuncAttributeMaxDynamicSharedMemorySize, ATTN_SMEM);
        attn_kernel<<<BATCH * NH * (T_SEQ / 32), 256, ATTN_SMEM>>>(posu, posv, mask, weights);
    }
    // 4) ctx = weights @ v
    {
        ctx_kernel<<<BATCH * NH * (T_SEQ / 64), 256>>>(weights);
    }
    // 5) out = ctx @ Wout^T + bout
    {
        dim3 grid(DMODEL / 128, BT / 128);
        sgemm_nt<<<grid, 256>>>(ctx_buf, Wout, bout, out, BT, DMODEL, DMODEL);
    }
}

// round 8
// speedup vs baseline: 1.9816x; 1.9816x over previous
#include <cuda_runtime.h>
#include <cstdint>

// Problem constants
#define BATCH   8
#define T_SEQ   512
#define DMODEL  1024
#define NH      16
#define DK      64
#define S_REL   1023          // 2T-1
#define BT      (BATCH*T_SEQ) // 4096
#define THREE_D (3*DMODEL)    // 3072

// Scratch (device globals; no allocation allowed)
__device__ float g_qkv[BT * THREE_D];   // [B,T, 3D]  (q | k | v per row)
__device__ float g_p[S_REL * DMODEL];   // [S, D] positional projection
__device__ float g_ctx[BT * DMODEL];    // [B,T,D] attention context

// ===========================================================================
// tf32 mma.sync GEMM (NT): C[M,N] = A[M,K] @ B[N,K]^T + bias[N]
// CTA tile 128x128, BK=32, 256 threads = 8 warps (4 m x 2 n), warp tile 32x64.
// Smem layout: row-major [row][kperm] with kperm=(k%4)*8+k/4, pitch 36 floats.
//  -> every mma fragment load is a contiguous, conflict-free LDS.128.
// Double-buffered; values converted to tf32 (cvt.rna) at STS time.
// Requires K % 32 == 0, N % 128 == 0. M may be ragged.
// ===========================================================================
#define PITCH 36
#define TILE_F (128 * PITCH)                   // floats per tile
#define GEMM_SMEM (2 * 2 * TILE_F * 4)         // 73728 bytes

__device__ __forceinline__ uint32_t f2tf32(float f) {
    uint32_t r;
    asm("cvt.rna.tf32.f32 %0, %1;" : "=r"(r) : "f"(f));
    return r;
}

__device__ __forceinline__ void mma_tf32(float* d,
                                         uint32_t a0, uint32_t a1, uint32_t a2, uint32_t a3,
                                         uint32_t b0, uint32_t b1) {
    asm volatile(
        "mma.sync.aligned.m16n8k8.row.col.f32.tf32.tf32.f32 "
        "{%0,%1,%2,%3}, {%4,%5,%6,%7}, {%8,%9}, {%0,%1,%2,%3};"
        : "+f"(d[0]), "+f"(d[1]), "+f"(d[2]), "+f"(d[3])
        : "r"(a0), "r"(a1), "r"(a2), "r"(a3), "r"(b0), "r"(b1));
}

__global__ __launch_bounds__(256, 1)
void gemm_tf32(const float* __restrict__ A, const float* __restrict__ Bm,
               const float* __restrict__ bias, float* __restrict__ C,
               int M, int N, int K)
{
    extern __shared__ __align__(16) float smem[];   // [2 stages][A|B][128*36]

    const int tid  = threadIdx.x;
    const int lane = tid & 31;
    const int w    = tid >> 5;
    const int wm   = w & 3;          // 0..3  (m warp)
    const int wn   = w >> 2;         // 0..1  (n warp)

    const int n0 = blockIdx.x * 128;
    const int m0 = blockIdx.y * 128;

    // loader mapping: per i in 0..3: row = w*8 + lane/4 + (i&1)*64,
    //                 q (k/4 group) = (lane&3) + 4*(i>>1)
    const int lrow = w * 8 + (lane >> 2);
    const int lq   = lane & 3;

    float acc[2][8][4];
#pragma unroll
    for (int mi = 0; mi < 2; mi++)
#pragma unroll
        for (int ni = 0; ni < 8; ni++)
#pragma unroll
            for (int r = 0; r < 4; r++) acc[mi][ni][r] = 0.f;

    const int nc = K >> 5;            // chunks of BK=32
    float4 sa[4], sb[4];

    // ---- prologue: load chunk 0 ----
#pragma unroll
    for (int i = 0; i < 4; i++) {
        int row = lrow + (i & 1) * 64;
        int q   = lq + 4 * (i >> 1);
        sa[i] = make_float4(0.f, 0.f, 0.f, 0.f);
        if (m0 + row < M)
            sa[i] = *(const float4*)(A + (size_t)(m0 + row) * K + q * 4);
        sb[i] = *(const float4*)(Bm + (size_t)(n0 + row) * K + q * 4);
    }
    {
        float* As = smem;
        float* Bs = smem + TILE_F;
#pragma unroll
        for (int i = 0; i < 4; i++) {
            int row = lrow + (i & 1) * 64;
            int q   = lq + 4 * (i >> 1);
            float* ar = As + row * PITCH + q;
            float* br = Bs + row * PITCH + q;
            ((uint32_t*)ar)[0]  = f2tf32(sa[i].x);
            ((uint32_t*)ar)[8]  = f2tf32(sa[i].y);
            ((uint32_t*)ar)[16] = f2tf32(sa[i].z);
            ((uint32_t*)ar)[24] = f2tf32(sa[i].w);
            ((uint32_t*)br)[0]  = f2tf32(sb[i].x);
            ((uint32_t*)br)[8]  = f2tf32(sb[i].y);
            ((uint32_t*)br)[16] = f2tf32(sb[i].z);
            ((uint32_t*)br)[24] = f2tf32(sb[i].w);
        }
    }
    __syncthreads();

    for (int c = 0; c < nc; c++) {
        // ---- prefetch next chunk to regs ----
        if (c + 1 < nc) {
            const int k0 = (c + 1) << 5;
#pragma unroll
            for (int i = 0; i < 4; i++) {
                int row = lrow + (i & 1) * 64;
                int q   = lq + 4 * (i >> 1);
                sa[i] = make_float4(0.f, 0.f, 0.f, 0.f);
                if (m0 + row < M)
                    sa[i] = *(const float4*)(A + (size_t)(m0 + row) * K + k0 + q * 4);
                sb[i] = *(const float4*)(Bm + (size_t)(n0 + row) * K + k0 + q * 4);
            }
        }

        // ---- load fragments for this chunk ----
        const float* As = smem + (c & 1) * 2 * TILE_F;
        const float* Bs = As + TILE_F;

        uint32_t ar[2][2][8];         // [mtile][rowhalf][j]
#pragma unroll
        for (int mi = 0; mi < 2; mi++)
#pragma unroll
            for (int h = 0; h < 2; h++) {
                int row = wm * 32 + mi * 16 + (lane >> 2) + h * 8;
                const float4* p = (const float4*)(As + row * PITCH + (lane & 3) * 8);
                float4 lo = p[0], hi = p[1];
                ar[mi][h][0] = __float_as_uint(lo.x);
                ar[mi][h][1] = __float_as_uint(lo.y);
                ar[mi][h][2] = __float_as_uint(lo.z);
                ar[mi][h][3] = __float_as_uint(lo.w);
                ar[mi][h][4] = __float_as_uint(hi.x);
                ar[mi][h][5] = __float_as_uint(hi.y);
                ar[mi][h][6] = __float_as_uint(hi.z);
                ar[mi][h][7] = __float_as_uint(hi.w);
            }
        uint32_t br[8][8];            // [ntile][j]
#pragma unroll
        for (int ni = 0; ni < 8; ni++) {
            int n = wn * 64 + ni * 8 + (lane >> 2);
            const float4* p = (const float4*)(Bs + n * PITCH + (lane & 3) * 8);
            float4 lo = p[0], hi = p[1];
            br[ni][0] = __float_as_uint(lo.x);
            br[ni][1] = __float_as_uint(lo.y);
            br[ni][2] = __float_as_uint(lo.z);
            br[ni][3] = __float_as_uint(lo.w);
            br[ni][4] = __float_as_uint(hi.x);
            br[ni][5] = __float_as_uint(hi.y);
            br[ni][6] = __float_as_uint(hi.z);
            br[ni][7] = __float_as_uint(hi.w);
        }

        // ---- 4 k-steps of m16n8k8 ----
#pragma unroll
        for (int ks = 0; ks < 4; ks++)
#pragma unroll
            for (int mi = 0; mi < 2; mi++)
#pragma unroll
                for (int ni = 0; ni < 8; ni++)
                    mma_tf32(acc[mi][ni],
                             ar[mi][0][2 * ks], ar[mi][1][2 * ks],
                             ar[mi][0][2 * ks + 1], ar[mi][1][2 * ks + 1],
                             br[ni][2 * ks], br[ni][2 * ks + 1]);

        // ---- store prefetched chunk into other buffer ----
        if (c + 1 < nc) {
            float* Asn = smem + ((c + 1) & 1) * 2 * TILE_F;
            float* Bsn = Asn + TILE_F;
#pragma unroll
            for (int i = 0; i < 4; i++) {
                int row = lrow + (i & 1) * 64;
                int q   = lq + 4 * (i >> 1);
                float* arp = Asn + row * PITCH + q;
                float* brp = Bsn + row * PITCH + q;
                ((uint32_t*)arp)[0]  = f2tf32(sa[i].x);
                ((uint32_t*)arp)[8]  = f2tf32(sa[i].y);
                ((uint32_t*)arp)[16] = f2tf32(sa[i].z);
                ((uint32_t*)arp)[24] = f2tf32(sa[i].w);
                ((uint32_t*)brp)[0]  = f2tf32(sb[i].x);
                ((uint32_t*)brp)[8]  = f2tf32(sb[i].y);
                ((uint32_t*)brp)[16] = f2tf32(sb[i].z);
                ((uint32_t*)brp)[24] = f2tf32(sb[i].w);
            }
            __syncthreads();
        }
    }

    // ---- epilogue ----
#pragma unroll
    for (int mi = 0; mi < 2; mi++) {
        int r0 = m0 + wm * 32 + mi * 16 + (lane >> 2);
#pragma unroll
        for (int ni = 0; ni < 8; ni++) {
            int cc = n0 + wn * 64 + ni * 8 + 2 * (lane & 3);
            float b0 = bias ? bias[cc]     : 0.f;
            float b1 = bias ? bias[cc + 1] : 0.f;
            if (r0 < M) {
                float2 v = make_float2(acc[mi][ni][0] + b0, acc[mi][ni][1] + b1);
                *(float2*)(C + (size_t)r0 * N + cc) = v;
            }
            if (r0 + 8 < M) {
                float2 v = make_float2(acc[mi][ni][2] + b0, acc[mi][ni][3] + b1);
                *(float2*)(C + (size_t)(r0 + 8) * N + cc) = v;
            }
        }
    }
}

// ---------------------------------------------------------------------------
// Attention: per block = (b, h, 32 query rows).  (round-2 champion, scalar)
//   AC[t,s]  = (q[t]+posu) . k[s]        (4 s-tiles of 128)
//   BD via diagonal GEMM: c[t,j] = (q[t]+posv) . p[j+511], scatter to s=t+j
// smem: qu(32x65) + qv(32x65) + buf(128x65) + scores(32x512)
// ---------------------------------------------------------------------------
#define ATTN_SMEM ((32*65*2 + 128*65 + 32*512) * 4)   // 115456 bytes

__global__ __launch_bounds__(256, 1)
void attn_kernel(const float* __restrict__ posu, const float* __restrict__ posv,
                 const int* __restrict__ mask,
                 float* __restrict__ weights)
{
    const int bid   = blockIdx.x;          // 2048 blocks
    const int ttile = bid & 15;
    const int h     = (bid >> 4) & 15;
    const int b     = bid >> 8;
    const int t0    = ttile * 32;

    extern __shared__ float sm[];
    float* qu  = sm;                 // 32 x 65
    float* qv  = qu + 32 * 65;       // 32 x 65
    float* buf = qv + 32 * 65;       // 128 x 65
    float* sc  = buf + 128 * 65;     // 32 x 512

    const int tid = threadIdx.x;
    const int tx  = tid & 31;
    const int ty  = tid >> 5;

#pragma unroll
    for (int i = 0; i < 8; i++) {
        int e  = i * 256 + tid;
        int tt = e >> 6;
        int d  = e & 63;
        float qval = g_qkv[(size_t)(b * T_SEQ + t0 + tt) * THREE_D + h * DK + d];
        qu[tt * 65 + d] = qval + posu[h * DK + d];
        qv[tt * 65 + d] = qval + posv[h * DK + d];
    }
    __syncthreads();

    for (int st = 0; st < 4; st++) {
        const int s0 = st * 128;
#pragma unroll
        for (int i = 0; i < 32; i++) {
            int e  = i * 256 + tid;
            int ss = e >> 6;
            int d  = e & 63;
            buf[ss * 65 + d] =
                g_qkv[(size_t)(b * T_SEQ + s0 + ss) * THREE_D + DMODEL + h * DK + d];
        }
        __syncthreads();

        float acc[4][4];
#pragma unroll
        for (int i = 0; i < 4; i++)
#pragma unroll
            for (int j = 0; j < 4; j++) acc[i][j] = 0.f;

#pragma unroll 8
        for (int d = 0; d < 64; d++) {
            float a0 = qu[(ty * 4 + 0) * 65 + d];
            float a1 = qu[(ty * 4 + 1) * 65 + d];
            float a2 = qu[(ty * 4 + 2) * 65 + d];
            float a3 = qu[(ty * 4 + 3) * 65 + d];
            float b0 = buf[(tx      ) * 65 + d];
            float b1 = buf[(tx +  32) * 65 + d];
            float b2 = buf[(tx +  64) * 65 + d];
            float b3 = buf[(tx +  96) * 65 + d];
            acc[0][0] += a0 * b0; acc[0][1] += a0 * b1; acc[0][2] += a0 * b2; acc[0][3] += a0 * b3;
            acc[1][0] += a1 * b0; acc[1][1] += a1 * b1; acc[1][2] += a1 * b2; acc[1][3] += a1 * b3;
            acc[2][0] += a2 * b0; acc[2][1] += a2 * b1; acc[2][2] += a2 * b2; acc[2][3] += a2 * b3;
            acc[3][0] += a3 * b0; acc[3][1] += a3 * b1; acc[3][2] += a3 * b2; acc[3][3] += a3 * b3;
        }
#pragma unroll
        for (int i = 0; i < 4; i++)
#pragma unroll
            for (int j = 0; j < 4; j++)
                sc[(ty * 4 + i) * 512 + s0 + tx + j * 32] = acc[i][j];
        __syncthreads();
    }

    const int jlo = -(t0 + 31);
    for (int jt = 0; jt < 5; jt++) {
        const int j0 = jlo + jt * 128;
#pragma unroll
        for (int i = 0; i < 32; i++) {
            int e = i * 256 + tid;
            int r = e >> 6;
            int d = e & 63;
            int prow = j0 + r + (T_SEQ - 1);
            buf[r * 65 + d] = (prow >= 0 && prow < S_REL)
                ? g_p[(size_t)prow * DMODEL + h * DK + d] : 0.f;
        }
        __syncthreads();

        float acc[4][4];
#pragma unroll
        for (int i = 0; i < 4; i++)
#pragma unroll
            for (int j = 0; j < 4; j++) acc[i][j] = 0.f;

#pragma unroll 8
        for (int d = 0; d < 64; d++) {
            float a0 = qv[(ty * 4 + 0) * 65 + d];
            float a1 = qv[(ty * 4 + 1) * 65 + d];
            float a2 = qv[(ty * 4 + 2) * 65 + d];
            float a3 = qv[(ty * 4 + 3) * 65 + d];
            float b0 = buf[(tx      ) * 65 + d];
            float b1 = buf[(tx +  32) * 65 + d];
            float b2 = buf[(tx +  64) * 65 + d];
            float b3 = buf[(tx +  96) * 65 + d];
            acc[0][0] += a0 * b0; acc[0][1] += a0 * b1; acc[0][2] += a0 * b2; acc[0][3] += a0 * b3;
            acc[1][0] += a1 * b0; acc[1][1] += a1 * b1; acc[1][2] += a1 * b2; acc[1][3] += a1 * b3;
            acc[2][0] += a2 * b0; acc[2][1] += a2 * b1; acc[2][2] += a2 * b2; acc[2][3] += a2 * b3;
            acc[3][0] += a3 * b0; acc[3][1] += a3 * b1; acc[3][2] += a3 * b2; acc[3][3] += a3 * b3;
        }
#pragma unroll
        for (int i = 0; i < 4; i++) {
            int tt = ty * 4 + i;
#pragma unroll
            for (int j = 0; j < 4; j++) {
                int jglob = j0 + tx + j * 32;
                int s = t0 + tt + jglob;
                if (s >= 0 && s < T_SEQ)
                    sc[tt * 512 + s] += acc[i][j];
            }
        }
        __syncthreads();
    }

    const int wid  = tid >> 5;
    const int lane = tid & 31;
#pragma unroll
    for (int rr = 0; rr < 4; rr++) {
        const int tt = wid * 4 + rr;
        const int t  = t0 + tt;
        const int* mrow = mask + ((size_t)b * T_SEQ + t) * T_SEQ;

        float mx = -3.4e38f;
        for (int c = lane; c < T_SEQ; c += 32) {
            float v = sc[tt * 512 + c] * 0.125f;
            v = mrow[c] ? v : -100000.0f;
            sc[tt * 512 + c] = v;
            mx = fmaxf(mx, v);
        }
#pragma unroll
        for (int off = 16; off > 0; off >>= 1)
            mx = fmaxf(mx, __shfl_xor_sync(0xffffffffu, mx, off));

        float sum = 0.f;
        for (int c = lane; c < T_SEQ; c += 32) {
            float e = __expf(sc[tt * 512 + c] - mx);
            sc[tt * 512 + c] = e;
            sum += e;
        }
#pragma unroll
        for (int off = 16; off > 0; off >>= 1)
            sum += __shfl_xor_sync(0xffffffffu, sum, off);
        float inv = 1.f / sum;

        float* wrow = weights + (((size_t)b * NH + h) * T_SEQ + t) * T_SEQ;
        for (int c = lane; c < T_SEQ; c += 32)
            wrow[c] = sc[tt * 512 + c] * inv;
    }
}

// ---------------------------------------------------------------------------
// ctx[b,t,h,:] = sum_s weights[b,h,t,s] * v[b,s,h,:]  (round-2 champion)
// ---------------------------------------------------------------------------
__global__ __launch_bounds__(256, 2)
void ctx_kernel(const float* __restrict__ weights)
{
    const int bid   = blockIdx.x;          // 1024 blocks
    const int ttile = bid & 7;
    const int h     = (bid >> 3) & 15;
    const int b     = bid >> 7;
    const int t0    = ttile * 64;

    __shared__ float ws[64][65];
    __shared__ float vs[64][65];

    const int tid = threadIdx.x;
    const int tx  = tid & 15;
    const int ty  = tid >> 4;

    float acc[4][4];
#pragma unroll
    for (int i = 0; i < 4; i++)
#pragma unroll
        for (int j = 0; j < 4; j++) acc[i][j] = 0.f;

    const float* wbase = weights + (((size_t)b * NH + h) * T_SEQ + t0) * T_SEQ;

    for (int s0 = 0; s0 < T_SEQ; s0 += 64) {
#pragma unroll
        for (int i = 0; i < 16; i++) {
            int e = i * 256 + tid;
            int r = e >> 6;
            int c = e & 63;
            ws[r][c] = wbase[(size_t)r * T_SEQ + s0 + c];
        }
#pragma unroll
        for (int i = 0; i < 16; i++) {
            int e = i * 256 + tid;
            int r = e >> 6;
            int c = e & 63;
            vs[r][c] = g_qkv[(size_t)(b * T_SEQ + s0 + r) * THREE_D + 2 * DMODEL + h * DK + c];
        }
        __syncthreads();
#pragma unroll 8
        for (int s = 0; s < 64; s++) {
            float a0 = ws[ty * 4 + 0][s];
            float a1 = ws[ty * 4 + 1][s];
            float a2 = ws[ty * 4 + 2][s];
            float a3 = ws[ty * 4 + 3][s];
            float b0 = vs[s][tx     ];
            float b1 = vs[s][tx + 16];
            float b2 = vs[s][tx + 32];
            float b3 = vs[s][tx + 48];
            acc[0][0] += a0 * b0; acc[0][1] += a0 * b1; acc[0][2] += a0 * b2; acc[0][3] += a0 * b3;
            acc[1][0] += a1 * b0; acc[1][1] += a1 * b1; acc[1][2] += a1 * b2; acc[1][3] += a1 * b3;
            acc[2][0] += a2 * b0; acc[2][1] += a2 * b1; acc[2][2] += a2 * b2; acc[2][3] += a2 * b3;
            acc[3][0] += a3 * b0; acc[3][1] += a3 * b1; acc[3][2] += a3 * b2; acc[3][3] += a3 * b3;
        }
        __syncthreads();
    }
#pragma unroll
    for (int i = 0; i < 4; i++) {
        int t = t0 + ty * 4 + i;
#pragma unroll
        for (int j = 0; j < 4; j++) {
            int d = tx + j * 16;
            g_ctx[(size_t)(b * T_SEQ + t) * DMODEL + h * DK + d] = acc[i][j];
        }
    }
}

// ---------------------------------------------------------------------------
extern "C" void kernel_launch(void* const* d_in, const int* in_sizes, int n_in,
                              void* d_out, int out_size)
{
    const float* x    = (const float*)d_in[0];
    const int*   mask = (const int*)d_in[1];
    const float* pos  = (const float*)d_in[2];
    const float* Wqkv = (const float*)d_in[3];
    const float* bqkv = (const float*)d_in[4];
    const float* Wpos = (const float*)d_in[5];
    const float* posu = (const float*)d_in[6];
    const float* posv = (const float*)d_in[7];
    const float* Wout = (const float*)d_in[8];
    const float* bout = (const float*)d_in[9];

    float* out     = (float*)d_out;
    float* weights = out + (size_t)BT * DMODEL;   // tuple: (out, weights)

    float* qkv_buf; cudaGetSymbolAddress((void**)&qkv_buf, g_qkv);
    float* p_buf;   cudaGetSymbolAddress((void**)&p_buf,   g_p);
    float* ctx_buf; cudaGetSymbolAddress((void**)&ctx_buf, g_ctx);

    cudaFuncSetAttribute(gemm_tf32,
                         cudaFuncAttributeMaxDynamicSharedMemorySize, GEMM_SMEM);
    cudaFuncSetAttribute(attn_kernel,
                         cudaFuncAttributeMaxDynamicSharedMemorySize, ATTN_SMEM);

    // 1) QKV projection: [4096,3072] = x @ Wqkv^T + bqkv   (tf32 mma)
    {
        dim3 grid(THREE_D / 128, BT / 128);
        gemm_tf32<<<grid, 256, GEMM_SMEM>>>(x, Wqkv, bqkv, qkv_buf, BT, THREE_D, DMODEL);
    }
    // 2) positional projection: [1023,1024] = pos @ Wpos^T (tf32 mma)
    {
        dim3 grid(DMODEL / 128, (S_REL + 127) / 128);
        gemm_tf32<<<grid, 256, GEMM_SMEM>>>(pos, Wpos, nullptr, p_buf, S_REL, DMODEL, DMODEL);
    }
    // 3) attention scores + softmax -> weights
    {
        attn_kernel<<<BATCH * NH * (T_SEQ / 32), 256, ATTN_SMEM>>>(posu, posv, mask, weights);
    }
    // 4) ctx = weights @ v
    {
        ctx_kernel<<<BATCH * NH * (T_SEQ / 64), 256>>>(weights);
    }
    // 5) out = ctx @ Wout^T + bout   (tf32 mma)
    {
        dim3 grid(DMODEL / 128, BT / 128);
        gemm_tf32<<<grid, 256, GEMM_SMEM>>>(ctx_buf, Wout, bout, out, BT, DMODEL, DMODEL);
    }
}